// round 5
// baseline (speedup 1.0000x reference)
#include <cuda_runtime.h>
#include <cuda_bf16.h>
#include <cstdint>

using u32 = uint32_t;

// ---------------- problem dims ----------------
constexpr int Mdim = 8192, Ndim = 4096, KL = 512, RANKS = 8;
constexpr int K3 = RANKS * KL * 3;            // 12288: split-bf16 3-term packed K

// ---------------- GEMM tiling ----------------
constexpr int BM = 128;                        // M per CTA
constexpr int BN = 256;                        // N per CTA
constexpr int BKB = 64;                        // bf16 k per SMEM stage (128B rows)
constexpr int NT = K3 / BKB;                   // 192 k-tiles
constexpr int THREADS = 256;                   // 8 warps: 2(m) x 4(n), warp tile 64x64

constexpr int A_BYTES = BM * 128;              // 16 KB
constexpr int B_BYTES = BN * 128;              // 32 KB
constexpr int STAGE_BYTES = A_BYTES + B_BYTES; // 48 KB
constexpr int STAGES = 4;
constexpr int SMEM_TOTAL = STAGES * STAGE_BYTES;   // 196608

// ---------------- scratch (device globals = sanctioned scratch) ----------------
__device__ __nv_bfloat16 g_A3[(size_t)Mdim * K3];   // 201 MB
__device__ __nv_bfloat16 g_B3[(size_t)Ndim * K3];   // 100 MB

// ---------------- PTX helpers (arch-portable, sm_80+) ----------------
__device__ __forceinline__ u32 smem_u32(const void* p) {
    u32 r;
    asm("{ .reg .u64 t; cvta.to.shared.u64 t, %1; cvt.u32.u64 %0, t; }"
        : "=r"(r) : "l"(p));
    return r;
}
__device__ __forceinline__ u32 swz128(u32 off) { return off ^ ((off >> 3) & 0x70); }

__device__ __forceinline__ void cp_async16(u32 saddr, const void* gaddr) {
    asm volatile("cp.async.cg.shared.global [%0], [%1], 16;"
                 :: "r"(saddr), "l"(gaddr) : "memory");
}
__device__ __forceinline__ void cp_commit() {
    asm volatile("cp.async.commit_group;" ::: "memory");
}
__device__ __forceinline__ void cp_wait2() {
    asm volatile("cp.async.wait_group 2;" ::: "memory");
}

__device__ __forceinline__ void ldsm_x4(u32& r0, u32& r1, u32& r2, u32& r3, u32 a) {
    asm volatile("ldmatrix.sync.aligned.m8n8.x4.shared.b16 {%0,%1,%2,%3}, [%4];"
                 : "=r"(r0), "=r"(r1), "=r"(r2), "=r"(r3) : "r"(a));
}
__device__ __forceinline__ void hmma_bf16(float* c, const u32* a, u32 b0, u32 b1) {
    asm volatile(
        "mma.sync.aligned.m16n8k16.row.col.f32.bf16.bf16.f32 "
        "{%0,%1,%2,%3}, {%4,%5,%6,%7}, {%8,%9}, {%0,%1,%2,%3};"
        : "+f"(c[0]), "+f"(c[1]), "+f"(c[2]), "+f"(c[3])
        : "r"(a[0]), "r"(a[1]), "r"(a[2]), "r"(a[3]), "r"(b0), "r"(b1));
}

// ---------------- conversion: fp32 -> split-bf16 triplets ----------------
// A3[m][(src*KL+k)*3 + {0,1,2}] = {hi, hi, lo}(a[src][m][k])
// B3[n][(src*KL+k)*3 + {0,1,2}] = {hi, lo, hi}(b[src][n][k])
// => sum = hi*hi + hi*lo + lo*hi  (drops lo*lo ~ 2^-18 relative)
__global__ void __launch_bounds__(256)
convert_kernel(const float* __restrict__ a, const float* __restrict__ b)
{
    constexpr size_t ACH = (size_t)RANKS * Mdim * KL / 8;   // 4,194,304
    constexpr size_t BCH = (size_t)RANKS * Ndim * KL / 8;   // 2,097,152
    size_t id = (size_t)blockIdx.x * 256 + threadIdx.x;
    if (id >= ACH + BCH) return;

    bool isA = id < ACH;
    size_t cid = isA ? id : id - ACH;

    size_t src_row = cid >> 6;            // 64 chunks of 8 floats per (src,row)
    int k0 = (int)(cid & 63) * 8;
    int srk, row;
    if (isA) { srk = (int)(src_row / Mdim); row = (int)(src_row % Mdim); }
    else     { srk = (int)(src_row / Ndim); row = (int)(src_row % Ndim); }

    const float* src = (isA ? a : b) + cid * 8;
    __nv_bfloat16* dst = (isA ? g_A3 : g_B3)
        + (size_t)row * K3 + (size_t)(srk * KL + k0) * 3;

    float4 f0 = ((const float4*)src)[0];
    float4 f1 = ((const float4*)src)[1];
    float xs[8] = {f0.x, f0.y, f0.z, f0.w, f1.x, f1.y, f1.z, f1.w};

    __align__(16) __nv_bfloat16 ov[24];
#pragma unroll
    for (int i = 0; i < 8; i++) {
        float x = xs[i];
        __nv_bfloat16 h = __float2bfloat16(x);
        __nv_bfloat16 l = __float2bfloat16(x - __bfloat162float(h));
        if (isA) { ov[3*i] = h; ov[3*i+1] = h; ov[3*i+2] = l; }
        else     { ov[3*i] = h; ov[3*i+1] = l; ov[3*i+2] = h; }
    }
    uint4* d4 = (uint4*)dst;
    const uint4* s4 = (const uint4*)ov;
    d4[0] = s4[0]; d4[1] = s4[1]; d4[2] = s4[2];
}

// ---------------- HMMA GEMM: C[8192,4096] = A3 @ B3^T ----------------
__global__ void __launch_bounds__(THREADS, 1)
gemm_mma_kernel(float* __restrict__ C)
{
    extern __shared__ __align__(1024) char smem[];
    const u32 sbase = smem_u32(smem);
    const int tid = threadIdx.x;
    const int lane = tid & 31;
    const int w = tid >> 5;            // 8 warps
    const int wm = w >> 2;             // 0..1 : warp row (64 M each)
    const int wn = w & 3;              // 0..3 : warp col (64 N each)

    const int m0 = blockIdx.y * BM;
    const int n0 = blockIdx.x * BN;

    // ---- cp.async mapping: per thread 4 A-chunks + 8 B-chunks per stage ----
    // chunk(i<4):  A row = (tid>>3) + i*32, col16 = tid&7
    // chunk(j<8):  B row = (tid>>3) + j*32, col16 = tid&7
    const int lrow = tid >> 3;                    // 0..31
    const int lcol = tid & 7;                     // 0..7
    const u32 sA0 = swz128((u32)lrow * 128 + (u32)lcol * 16);
    const u32 sB0 = A_BYTES + sA0;                // same swizzle key (row&7 equal)
    const __nv_bfloat16* gA = g_A3 + (size_t)(m0 + lrow) * K3 + lcol * 8;
    const __nv_bfloat16* gB = g_B3 + (size_t)(n0 + lrow) * K3 + lcol * 8;
    constexpr size_t RSTRIDE = (size_t)32 * K3;   // 32-row pointer stride

    // ---- ldmatrix address precomputation ----
    // smem addr = rowbase + ((kbyte + khalf) ^ ((lane&7)*16)); row&7 == lane&7.
    const u32 frag_xor = (u32)(lane & 7) * 16;
    const u32 khalf = (u32)((lane >> 4) & 1) * 16;
    const int frag_row = (((lane >> 3) & 1) << 3) + (lane & 7);
    u32 aPre[4];
#pragma unroll
    for (int mb = 0; mb < 4; mb++)
        aPre[mb] = (u32)(wm * 64 + mb * 16 + frag_row) * 128;
    u32 bPre[4];
#pragma unroll
    for (int nb = 0; nb < 4; nb++)
        bPre[nb] = (u32)(wn * 64 + nb * 16 + frag_row) * 128;

    float acc[4][8][4];
#pragma unroll
    for (int i = 0; i < 4; i++)
#pragma unroll
        for (int j = 0; j < 8; j++)
#pragma unroll
            for (int q = 0; q < 4; q++) acc[i][j][q] = 0.f;

    // ---- prologue: stage tiles 0..2 ----
#pragma unroll
    for (int p = 0; p < 3; p++) {
        const u32 sb = sbase + p * STAGE_BYTES;
#pragma unroll
        for (int i = 0; i < 4; i++)
            cp_async16(sb + sA0 + i * 4096, gA + (size_t)i * RSTRIDE + (size_t)p * BKB);
#pragma unroll
        for (int j = 0; j < 8; j++)
            cp_async16(sb + sB0 + j * 4096, gB + (size_t)j * RSTRIDE + (size_t)p * BKB);
        cp_commit();
    }

    // ---- main loop: ONE barrier per tile ----
    // iter t: wait(group t) ; sync ; compute(t) ; prefetch(t+3) ; commit
    // WAR safe: prefetch writes stage (t+3)&3 == (t-1)&3, whose readers
    // (compute t-1) are all before this iteration's __syncthreads.
    for (int t = 0; t < NT; t++) {
        cp_wait2();                // group t complete (own thread)
        __syncthreads();           // all threads' chunks of tile t visible

        const u32 sA = sbase + (t & 3) * STAGE_BYTES;
        const u32 sB = sA + A_BYTES;

#pragma unroll
        for (int ks = 0; ks < 4; ks++) {
            const u32 kk = ((u32)ks * 32 + khalf) ^ frag_xor;
            u32 af[4][4];
#pragma unroll
            for (int mb = 0; mb < 4; mb++)
                ldsm_x4(af[mb][0], af[mb][1], af[mb][2], af[mb][3], sA + aPre[mb] + kk);
            u32 bf[4][4];   // per nb16: {n0k0, n8k0, n0k8, n8k8}
#pragma unroll
            for (int nb = 0; nb < 4; nb++)
                ldsm_x4(bf[nb][0], bf[nb][1], bf[nb][2], bf[nb][3], sB + bPre[nb] + kk);
#pragma unroll
            for (int mb = 0; mb < 4; mb++)
#pragma unroll
                for (int nb = 0; nb < 4; nb++) {
                    hmma_bf16(acc[mb][2 * nb + 0], af[mb], bf[nb][0], bf[nb][2]);
                    hmma_bf16(acc[mb][2 * nb + 1], af[mb], bf[nb][1], bf[nb][3]);
                }
        }

        if (t + 3 < NT) {
            const u32 sb = sbase + ((t + 3) & 3) * STAGE_BYTES;
#pragma unroll
            for (int i = 0; i < 4; i++)
                cp_async16(sb + sA0 + i * 4096,
                           gA + (size_t)i * RSTRIDE + (size_t)(t + 3) * BKB);
#pragma unroll
            for (int j = 0; j < 8; j++)
                cp_async16(sb + sB0 + j * 4096,
                           gB + (size_t)j * RSTRIDE + (size_t)(t + 3) * BKB);
        }
        cp_commit();               // one group per iter (empty near tail)
    }

    // ---- epilogue ----
    const int er = lane >> 2;
    const int ec = (lane & 3) * 2;
#pragma unroll
    for (int mb = 0; mb < 4; mb++) {
#pragma unroll
        for (int nb = 0; nb < 8; nb++) {
            float* base = C + (size_t)(m0 + wm * 64 + mb * 16 + er) * Ndim
                            + (n0 + wn * 64 + nb * 8 + ec);
            *(float2*)base = make_float2(acc[mb][nb][0], acc[mb][nb][1]);
            *(float2*)(base + (size_t)8 * Ndim) = make_float2(acc[mb][nb][2], acc[mb][nb][3]);
        }
    }
}

// ---------------- launch ----------------
extern "C" void kernel_launch(void* const* d_in, const int* in_sizes, int n_in,
                              void* d_out, int out_size)
{
    const float* a = (const float*)d_in[0];   // [8, 8192, 512] fp32
    const float* b = (const float*)d_in[1];   // [8, 4096, 512] fp32
    float* c = (float*)d_out;                 // [8192, 4096] fp32

    constexpr size_t TOTAL_CHUNKS =
        ((size_t)RANKS * Mdim * KL + (size_t)RANKS * Ndim * KL) / 8;  // 6,291,456
    convert_kernel<<<(unsigned)(TOTAL_CHUNKS / 256), 256>>>(a, b);

    cudaFuncSetAttribute(gemm_mma_kernel,
                         cudaFuncAttributeMaxDynamicSharedMemorySize, SMEM_TOTAL);
    dim3 grid(Ndim / BN, Mdim / BM);          // (16, 64) = 1024 CTAs
    gemm_mma_kernel<<<grid, THREADS, SMEM_TOTAL>>>(c);
}

// round 6
// speedup vs baseline: 1.3958x; 1.3958x over previous
#include <cuda_runtime.h>
#include <cuda_fp16.h>
#include <cstdint>

using u32 = uint32_t;

// ---------------- problem dims ----------------
constexpr int Mdim = 8192, Ndim = 4096, KL = 512, RANKS = 8;
constexpr int K2 = RANKS * KL * 2;            // 8192: fp16 2-term packed K

// ---------------- GEMM tiling ----------------
constexpr int BM = 256;                        // M per CTA
constexpr int BN = 128;                        // N per CTA
constexpr int BKB = 64;                        // fp16 k per SMEM stage (128B rows)
constexpr int NT = K2 / BKB;                   // 128 k-tiles
constexpr int THREADS = 512;                   // 16 warps: 4(m) x 4(n), warp 64x32

constexpr int A_BYTES = BM * 128;              // 32 KB
constexpr int B_BYTES = BN * 128;              // 16 KB
constexpr int STAGE_BYTES = A_BYTES + B_BYTES; // 48 KB
constexpr int STAGES = 4;
constexpr int SMEM_TOTAL = STAGES * STAGE_BYTES;   // 196608

// ---------------- scratch (device globals = sanctioned scratch) ----------------
__device__ __half g_A2[(size_t)Mdim * K2];   // 134 MB : {hi, lo} pairs
__device__ __half g_B2[(size_t)Ndim * K2];   //  67 MB : {hi, hi} pairs

// ---------------- PTX helpers (arch-portable, sm_80+) ----------------
__device__ __forceinline__ u32 smem_u32(const void* p) {
    u32 r;
    asm("{ .reg .u64 t; cvta.to.shared.u64 t, %1; cvt.u32.u64 %0, t; }"
        : "=r"(r) : "l"(p));
    return r;
}
__device__ __forceinline__ u32 swz128(u32 off) { return off ^ ((off >> 3) & 0x70); }

__device__ __forceinline__ void cp_async16(u32 saddr, const void* gaddr) {
    asm volatile("cp.async.cg.shared.global [%0], [%1], 16;"
                 :: "r"(saddr), "l"(gaddr) : "memory");
}
__device__ __forceinline__ void cp_commit() {
    asm volatile("cp.async.commit_group;" ::: "memory");
}
__device__ __forceinline__ void cp_wait2() {
    asm volatile("cp.async.wait_group 2;" ::: "memory");
}

__device__ __forceinline__ void ldsm_x4(u32& r0, u32& r1, u32& r2, u32& r3, u32 a) {
    asm volatile("ldmatrix.sync.aligned.m8n8.x4.shared.b16 {%0,%1,%2,%3}, [%4];"
                 : "=r"(r0), "=r"(r1), "=r"(r2), "=r"(r3) : "r"(a));
}
__device__ __forceinline__ void hmma_f16(float* c, const u32* a, u32 b0, u32 b1) {
    asm volatile(
        "mma.sync.aligned.m16n8k16.row.col.f32.f16.f16.f32 "
        "{%0,%1,%2,%3}, {%4,%5,%6,%7}, {%8,%9}, {%0,%1,%2,%3};"
        : "+f"(c[0]), "+f"(c[1]), "+f"(c[2]), "+f"(c[3])
        : "r"(a[0]), "r"(a[1]), "r"(a[2]), "r"(a[3]), "r"(b0), "r"(b1));
}

// ---------------- conversion: fp32 -> fp16 2-term ----------------
// A2[m][(src*KL+k)*2 + {0,1}] = {hi, lo}(a)   with hi=fl16(a), lo=fl16(a-hi)
// B2[n][(src*KL+k)*2 + {0,1}] = {hi, hi}(b)
// => sum = (hi_a+lo_a)*hi_b ~= a*fl16(b); error = a*(b - fl16(b)) ~ 2^-11/sqrt(3)
__global__ void __launch_bounds__(256)
convert_kernel(const float* __restrict__ a, const float* __restrict__ b)
{
    constexpr size_t ACH = (size_t)RANKS * Mdim * KL / 8;   // 4,194,304
    constexpr size_t BCH = (size_t)RANKS * Ndim * KL / 8;   // 2,097,152
    size_t id = (size_t)blockIdx.x * 256 + threadIdx.x;
    if (id >= ACH + BCH) return;

    bool isA = id < ACH;
    size_t cid = isA ? id : id - ACH;

    size_t src_row = cid >> 6;            // 64 chunks of 8 floats per (src,row)
    int k0 = (int)(cid & 63) * 8;
    int srk, row;
    if (isA) { srk = (int)(src_row / Mdim); row = (int)(src_row % Mdim); }
    else     { srk = (int)(src_row / Ndim); row = (int)(src_row % Ndim); }

    const float* src = (isA ? a : b) + cid * 8;
    __half* dst = (isA ? g_A2 : g_B2)
        + (size_t)row * K2 + (size_t)(srk * KL + k0) * 2;

    float4 f0 = ((const float4*)src)[0];
    float4 f1 = ((const float4*)src)[1];
    float xs[8] = {f0.x, f0.y, f0.z, f0.w, f1.x, f1.y, f1.z, f1.w};

    __align__(16) __half ov[16];
#pragma unroll
    for (int i = 0; i < 8; i++) {
        float x = xs[i];
        __half h = __float2half_rn(x);
        if (isA) {
            __half l = __float2half_rn(x - __half2float(h));
            ov[2*i] = h; ov[2*i+1] = l;
        } else {
            ov[2*i] = h; ov[2*i+1] = h;
        }
    }
    uint4* d4 = (uint4*)dst;
    const uint4* s4 = (const uint4*)ov;
    d4[0] = s4[0]; d4[1] = s4[1];
}

// ---------------- HMMA GEMM: C[8192,4096] = A2 @ B2^T ----------------
__global__ void __launch_bounds__(THREADS, 1)
gemm_mma_kernel(float* __restrict__ C)
{
    extern __shared__ __align__(1024) char smem[];
    const u32 sbase = smem_u32(smem);
    const int tid = threadIdx.x;
    const int lane = tid & 31;
    const int w = tid >> 5;            // 16 warps
    const int wm = w >> 2;             // 0..3 : warp row (64 M each)
    const int wn = w & 3;              // 0..3 : warp col (32 N each)

    const int m0 = blockIdx.y * BM;
    const int n0 = blockIdx.x * BN;

    // ---- cp.async mapping: 6 chunks/thread/stage (4 A + 2 B) ----
    const int lrow = tid >> 3;                    // 0..63
    const int lcol = tid & 7;                     // 0..7
    const u32 sA0 = swz128((u32)lrow * 128 + (u32)lcol * 16);
    const u32 sB0 = A_BYTES + sA0;                // same swizzle key (row&7 equal)
    const __half* gA = g_A2 + (size_t)(m0 + lrow) * K2 + lcol * 8;
    const __half* gB = g_B2 + (size_t)(n0 + lrow) * K2 + lcol * 8;
    constexpr size_t RSTRIDE = (size_t)64 * K2;   // 64-row pointer stride

    // ---- ldmatrix address precomputation ----
    const u32 frag_xor = (u32)(lane & 7) * 16;
    const u32 khalf = (u32)((lane >> 4) & 1) * 16;
    const int frag_row = (((lane >> 3) & 1) << 3) + (lane & 7);
    u32 aPre[4];
#pragma unroll
    for (int mb = 0; mb < 4; mb++)
        aPre[mb] = (u32)(wm * 64 + mb * 16 + frag_row) * 128;
    u32 bPre[2];
#pragma unroll
    for (int nb = 0; nb < 2; nb++)
        bPre[nb] = (u32)(wn * 32 + nb * 16 + frag_row) * 128;

    float acc[4][4][4];
#pragma unroll
    for (int i = 0; i < 4; i++)
#pragma unroll
        for (int j = 0; j < 4; j++)
#pragma unroll
            for (int q = 0; q < 4; q++) acc[i][j][q] = 0.f;

    // ---- prologue: stage tiles 0..2 ----
#pragma unroll
    for (int p = 0; p < 3; p++) {
        const u32 sb = sbase + p * STAGE_BYTES;
#pragma unroll
        for (int i = 0; i < 4; i++)
            cp_async16(sb + sA0 + i * 8192, gA + (size_t)i * RSTRIDE + (size_t)p * BKB);
#pragma unroll
        for (int j = 0; j < 2; j++)
            cp_async16(sb + sB0 + j * 8192, gB + (size_t)j * RSTRIDE + (size_t)p * BKB);
        cp_commit();
    }

    // ---- main loop: ONE barrier per tile, prefetch issued before compute ----
    // WAR safe: prefetch writes stage (t+3)&3 == (t-1)&3, whose readers
    // (compute t-1) all precede this iteration's __syncthreads.
    for (int t = 0; t < NT; t++) {
        cp_wait2();                // group t complete (own thread)
        __syncthreads();           // all threads' chunks of tile t visible

        if (t + 3 < NT) {
            const u32 sb = sbase + ((t + 3) & 3) * STAGE_BYTES;
#pragma unroll
            for (int i = 0; i < 4; i++)
                cp_async16(sb + sA0 + i * 8192,
                           gA + (size_t)i * RSTRIDE + (size_t)(t + 3) * BKB);
#pragma unroll
            for (int j = 0; j < 2; j++)
                cp_async16(sb + sB0 + j * 8192,
                           gB + (size_t)j * RSTRIDE + (size_t)(t + 3) * BKB);
        }
        cp_commit();               // one group per iter (empty near tail)

        const u32 sA = sbase + (t & 3) * STAGE_BYTES;
        const u32 sB = sA + A_BYTES;

#pragma unroll
        for (int ks = 0; ks < 4; ks++) {
            const u32 kk = ((u32)ks * 32 + khalf) ^ frag_xor;
            u32 af[4][4];
#pragma unroll
            for (int mb = 0; mb < 4; mb++)
                ldsm_x4(af[mb][0], af[mb][1], af[mb][2], af[mb][3], sA + aPre[mb] + kk);
            u32 bf[2][4];   // per nb16: {n0k0, n8k0, n0k8, n8k8}
#pragma unroll
            for (int nb = 0; nb < 2; nb++)
                ldsm_x4(bf[nb][0], bf[nb][1], bf[nb][2], bf[nb][3], sB + bPre[nb] + kk);
#pragma unroll
            for (int mb = 0; mb < 4; mb++)
#pragma unroll
                for (int nb = 0; nb < 2; nb++) {
                    hmma_f16(acc[mb][2 * nb + 0], af[mb], bf[nb][0], bf[nb][2]);
                    hmma_f16(acc[mb][2 * nb + 1], af[mb], bf[nb][1], bf[nb][3]);
                }
        }
    }

    // ---- epilogue ----
    const int er = lane >> 2;
    const int ec = (lane & 3) * 2;
#pragma unroll
    for (int mb = 0; mb < 4; mb++) {
#pragma unroll
        for (int nb = 0; nb < 4; nb++) {
            float* base = C + (size_t)(m0 + wm * 64 + mb * 16 + er) * Ndim
                            + (n0 + wn * 32 + nb * 8 + ec);
            *(float2*)base = make_float2(acc[mb][nb][0], acc[mb][nb][1]);
            *(float2*)(base + (size_t)8 * Ndim) = make_float2(acc[mb][nb][2], acc[mb][nb][3]);
        }
    }
}

// ---------------- launch ----------------
extern "C" void kernel_launch(void* const* d_in, const int* in_sizes, int n_in,
                              void* d_out, int out_size)
{
    const float* a = (const float*)d_in[0];   // [8, 8192, 512] fp32
    const float* b = (const float*)d_in[1];   // [8, 4096, 512] fp32
    float* c = (float*)d_out;                 // [8192, 4096] fp32

    constexpr size_t TOTAL_CHUNKS =
        ((size_t)RANKS * Mdim * KL + (size_t)RANKS * Ndim * KL) / 8;  // 6,291,456
    convert_kernel<<<(unsigned)(TOTAL_CHUNKS / 256), 256>>>(a, b);

    cudaFuncSetAttribute(gemm_mma_kernel,
                         cudaFuncAttributeMaxDynamicSharedMemorySize, SMEM_TOTAL);
    dim3 grid(Ndim / BN, Mdim / BM);          // (32, 32) = 1024 CTAs
    gemm_mma_kernel<<<grid, THREADS, SMEM_TOTAL>>>(c);
}

// round 7
// speedup vs baseline: 2.6909x; 1.9278x over previous
#include <cuda_runtime.h>
#include <cuda_fp16.h>
#include <cstdint>

using u32 = uint32_t;

// ---------------- problem dims ----------------
constexpr int Mdim = 8192, Ndim = 4096, KL = 512, RANKS = 8;
constexpr int K4 = RANKS * KL;                 // 4096: plain fp16, 1:1 K packing

// ---------------- GEMM tiling ----------------
constexpr int BM = 256;                        // M per CTA
constexpr int BN = 128;                        // N per CTA
constexpr int BKB = 64;                        // fp16 k per SMEM stage (128B rows)
constexpr int NT = K4 / BKB;                   // 64 k-tiles
constexpr int THREADS = 512;                   // 16 warps: 4(m) x 4(n), warp 64x32

constexpr int A_BYTES = BM * 128;              // 32 KB
constexpr int B_BYTES = BN * 128;              // 16 KB
constexpr int STAGE_BYTES = A_BYTES + B_BYTES; // 48 KB
constexpr int STAGES = 4;
constexpr int SMEM_TOTAL = STAGES * STAGE_BYTES;   // 196608

// ---------------- scratch (device globals = sanctioned scratch) ----------------
__device__ __half g_A2[(size_t)Mdim * K4];   // 67 MB : fl16(a)
__device__ __half g_B2[(size_t)Ndim * K4];   // 33 MB : fl16(b)

// ---------------- PTX helpers (arch-portable, sm_80+) ----------------
__device__ __forceinline__ u32 smem_u32(const void* p) {
    u32 r;
    asm("{ .reg .u64 t; cvta.to.shared.u64 t, %1; cvt.u32.u64 %0, t; }"
        : "=r"(r) : "l"(p));
    return r;
}
__device__ __forceinline__ u32 swz128(u32 off) { return off ^ ((off >> 3) & 0x70); }

__device__ __forceinline__ void cp_async16(u32 saddr, const void* gaddr) {
    asm volatile("cp.async.cg.shared.global [%0], [%1], 16;"
                 :: "r"(saddr), "l"(gaddr) : "memory");
}
__device__ __forceinline__ void cp_commit() {
    asm volatile("cp.async.commit_group;" ::: "memory");
}
__device__ __forceinline__ void cp_wait2() {
    asm volatile("cp.async.wait_group 2;" ::: "memory");
}

__device__ __forceinline__ void ldsm_x4(u32& r0, u32& r1, u32& r2, u32& r3, u32 a) {
    asm volatile("ldmatrix.sync.aligned.m8n8.x4.shared.b16 {%0,%1,%2,%3}, [%4];"
                 : "=r"(r0), "=r"(r1), "=r"(r2), "=r"(r3) : "r"(a));
}
__device__ __forceinline__ void hmma_f16(float* c, const u32* a, u32 b0, u32 b1) {
    asm volatile(
        "mma.sync.aligned.m16n8k16.row.col.f32.f16.f16.f32 "
        "{%0,%1,%2,%3}, {%4,%5,%6,%7}, {%8,%9}, {%0,%1,%2,%3};"
        : "+f"(c[0]), "+f"(c[1]), "+f"(c[2]), "+f"(c[3])
        : "r"(a[0]), "r"(a[1]), "r"(a[2]), "r"(a[3]), "r"(b0), "r"(b1));
}

// ---------------- conversion: fp32 -> fp16 (1:1) ----------------
// A2[m][src*KL + k] = fl16(a[src][m][k]);  B2[n][src*KL + k] = fl16(b[src][n][k])
// C error = sum a*eps_b + b*eps_a  ->  ~sqrt(2) * 2.08e-4 ~= 2.9e-4 << 1e-3
__global__ void __launch_bounds__(256)
convert_kernel(const float* __restrict__ a, const float* __restrict__ b)
{
    constexpr size_t ACH = (size_t)RANKS * Mdim * KL / 8;   // 4,194,304
    constexpr size_t BCH = (size_t)RANKS * Ndim * KL / 8;   // 2,097,152
    size_t id = (size_t)blockIdx.x * 256 + threadIdx.x;
    if (id >= ACH + BCH) return;

    bool isA = id < ACH;
    size_t cid = isA ? id : id - ACH;

    size_t src_row = cid >> 6;            // 64 chunks of 8 floats per (src,row)
    int k0 = (int)(cid & 63) * 8;
    int srk, row;
    if (isA) { srk = (int)(src_row / Mdim); row = (int)(src_row % Mdim); }
    else     { srk = (int)(src_row / Ndim); row = (int)(src_row % Ndim); }

    const float* src = (isA ? a : b) + cid * 8;
    __half* dst = (isA ? g_A2 : g_B2)
        + (size_t)row * K4 + (size_t)(srk * KL + k0);

    float4 f0 = ((const float4*)src)[0];
    float4 f1 = ((const float4*)src)[1];
    float xs[8] = {f0.x, f0.y, f0.z, f0.w, f1.x, f1.y, f1.z, f1.w};

    __align__(16) __half ov[8];
#pragma unroll
    for (int i = 0; i < 8; i++) ov[i] = __float2half_rn(xs[i]);
    *(uint4*)dst = *(const uint4*)ov;
}

// ---------------- HMMA GEMM: C[8192,4096] = A2 @ B2^T ----------------
__global__ void __launch_bounds__(THREADS, 1)
gemm_mma_kernel(float* __restrict__ C)
{
    extern __shared__ __align__(1024) char smem[];
    const u32 sbase = smem_u32(smem);
    const int tid = threadIdx.x;
    const int lane = tid & 31;
    const int w = tid >> 5;            // 16 warps
    const int wm = w >> 2;             // 0..3 : warp row (64 M each)
    const int wn = w & 3;              // 0..3 : warp col (32 N each)

    const int m0 = blockIdx.y * BM;
    const int n0 = blockIdx.x * BN;

    // ---- cp.async mapping: 6 chunks/thread/stage (4 A + 2 B) ----
    const int lrow = tid >> 3;                    // 0..63
    const int lcol = tid & 7;                     // 0..7
    const u32 sA0 = swz128((u32)lrow * 128 + (u32)lcol * 16);
    const u32 sB0 = A_BYTES + sA0;                // same swizzle key (row&7 equal)
    const __half* gA = g_A2 + (size_t)(m0 + lrow) * K4 + lcol * 8;
    const __half* gB = g_B2 + (size_t)(n0 + lrow) * K4 + lcol * 8;
    constexpr size_t RSTRIDE = (size_t)64 * K4;   // 64-row pointer stride

    // ---- ldmatrix address precomputation ----
    const u32 frag_xor = (u32)(lane & 7) * 16;
    const u32 khalf = (u32)((lane >> 4) & 1) * 16;
    const int frag_row = (((lane >> 3) & 1) << 3) + (lane & 7);
    u32 aPre[4];
#pragma unroll
    for (int mb = 0; mb < 4; mb++)
        aPre[mb] = (u32)(wm * 64 + mb * 16 + frag_row) * 128;
    u32 bPre[2];
#pragma unroll
    for (int nb = 0; nb < 2; nb++)
        bPre[nb] = (u32)(wn * 32 + nb * 16 + frag_row) * 128;

    float acc[4][4][4];
#pragma unroll
    for (int i = 0; i < 4; i++)
#pragma unroll
        for (int j = 0; j < 4; j++)
#pragma unroll
            for (int q = 0; q < 4; q++) acc[i][j][q] = 0.f;

    // ---- prologue: stage tiles 0..2 ----
#pragma unroll
    for (int p = 0; p < 3; p++) {
        const u32 sb = sbase + p * STAGE_BYTES;
#pragma unroll
        for (int i = 0; i < 4; i++)
            cp_async16(sb + sA0 + i * 8192, gA + (size_t)i * RSTRIDE + (size_t)p * BKB);
#pragma unroll
        for (int j = 0; j < 2; j++)
            cp_async16(sb + sB0 + j * 8192, gB + (size_t)j * RSTRIDE + (size_t)p * BKB);
        cp_commit();
    }

    // ---- main loop: ONE barrier per tile, prefetch issued before compute ----
    // WAR safe: prefetch writes stage (t+3)&3 == (t-1)&3, whose readers
    // (compute t-1) all precede this iteration's __syncthreads.
    for (int t = 0; t < NT; t++) {
        cp_wait2();                // group t complete (own thread)
        __syncthreads();           // all threads' chunks of tile t visible

        if (t + 3 < NT) {
            const u32 sb = sbase + ((t + 3) & 3) * STAGE_BYTES;
#pragma unroll
            for (int i = 0; i < 4; i++)
                cp_async16(sb + sA0 + i * 8192,
                           gA + (size_t)i * RSTRIDE + (size_t)(t + 3) * BKB);
#pragma unroll
            for (int j = 0; j < 2; j++)
                cp_async16(sb + sB0 + j * 8192,
                           gB + (size_t)j * RSTRIDE + (size_t)(t + 3) * BKB);
        }
        cp_commit();               // one group per iter (empty near tail)

        const u32 sA = sbase + (t & 3) * STAGE_BYTES;
        const u32 sB = sA + A_BYTES;

#pragma unroll
        for (int ks = 0; ks < 4; ks++) {
            const u32 kk = ((u32)ks * 32 + khalf) ^ frag_xor;
            u32 af[4][4];
#pragma unroll
            for (int mb = 0; mb < 4; mb++)
                ldsm_x4(af[mb][0], af[mb][1], af[mb][2], af[mb][3], sA + aPre[mb] + kk);
            u32 bf[2][4];   // per nb16: {n0k0, n8k0, n0k8, n8k8}
#pragma unroll
            for (int nb = 0; nb < 2; nb++)
                ldsm_x4(bf[nb][0], bf[nb][1], bf[nb][2], bf[nb][3], sB + bPre[nb] + kk);
#pragma unroll
            for (int mb = 0; mb < 4; mb++)
#pragma unroll
                for (int nb = 0; nb < 2; nb++) {
                    hmma_f16(acc[mb][2 * nb + 0], af[mb], bf[nb][0], bf[nb][2]);
                    hmma_f16(acc[mb][2 * nb + 1], af[mb], bf[nb][1], bf[nb][3]);
                }
        }
    }

    // ---- epilogue ----
    const int er = lane >> 2;
    const int ec = (lane & 3) * 2;
#pragma unroll
    for (int mb = 0; mb < 4; mb++) {
#pragma unroll
        for (int nb = 0; nb < 4; nb++) {
            float* base = C + (size_t)(m0 + wm * 64 + mb * 16 + er) * Ndim
                            + (n0 + wn * 32 + nb * 8 + ec);
            *(float2*)base = make_float2(acc[mb][nb][0], acc[mb][nb][1]);
            *(float2*)(base + (size_t)8 * Ndim) = make_float2(acc[mb][nb][2], acc[mb][nb][3]);
        }
    }
}

// ---------------- launch ----------------
extern "C" void kernel_launch(void* const* d_in, const int* in_sizes, int n_in,
                              void* d_out, int out_size)
{
    const float* a = (const float*)d_in[0];   // [8, 8192, 512] fp32
    const float* b = (const float*)d_in[1];   // [8, 4096, 512] fp32
    float* c = (float*)d_out;                 // [8192, 4096] fp32

    constexpr size_t TOTAL_CHUNKS =
        ((size_t)RANKS * Mdim * KL + (size_t)RANKS * Ndim * KL) / 8;  // 6,291,456
    convert_kernel<<<(unsigned)(TOTAL_CHUNKS / 256), 256>>>(a, b);

    cudaFuncSetAttribute(gemm_mma_kernel,
                         cudaFuncAttributeMaxDynamicSharedMemorySize, SMEM_TOTAL);
    dim3 grid(Ndim / BN, Mdim / BM);          // (32, 32) = 1024 CTAs
    gemm_mma_kernel<<<grid, THREADS, SMEM_TOTAL>>>(c);
}

// round 8
// speedup vs baseline: 2.8977x; 1.0769x over previous
#include <cuda_runtime.h>
#include <cuda_fp16.h>
#include <cstdint>

using u32 = uint32_t;

// ---------------- problem dims ----------------
constexpr int Mdim = 8192, Ndim = 4096, KL = 512, RANKS = 8;
constexpr int K4 = RANKS * KL;                 // 4096: plain fp16, 1:1 K packing

// ---------------- GEMM tiling ----------------
constexpr int BM = 128;                        // M per CTA
constexpr int BN = 128;                        // N per CTA
constexpr int BKB = 64;                        // fp16 k per SMEM stage (128B rows)
constexpr int NT = K4 / BKB;                   // 64 k-tiles
constexpr int THREADS = 256;                   // 8 warps: 2(m) x 4(n), warp 64x32

constexpr int A_BYTES = BM * 128;              // 16 KB
constexpr int B_BYTES = BN * 128;              // 16 KB
constexpr int STAGE_BYTES = A_BYTES + B_BYTES; // 32 KB
constexpr int STAGES = 3;
constexpr int SMEM_TOTAL = STAGES * STAGE_BYTES;   // 98304 -> 2 CTAs/SM

// ---------------- scratch (device globals = sanctioned scratch) ----------------
__device__ __half g_A2[(size_t)Mdim * K4];   // 67 MB : fl16(a)
__device__ __half g_B2[(size_t)Ndim * K4];   // 33 MB : fl16(b)

// ---------------- PTX helpers (arch-portable, sm_80+) ----------------
__device__ __forceinline__ u32 smem_u32(const void* p) {
    u32 r;
    asm("{ .reg .u64 t; cvta.to.shared.u64 t, %1; cvt.u32.u64 %0, t; }"
        : "=r"(r) : "l"(p));
    return r;
}
__device__ __forceinline__ u32 swz128(u32 off) { return off ^ ((off >> 3) & 0x70); }

__device__ __forceinline__ void cp_async16(u32 saddr, const void* gaddr) {
    asm volatile("cp.async.cg.shared.global [%0], [%1], 16;"
                 :: "r"(saddr), "l"(gaddr) : "memory");
}
__device__ __forceinline__ void cp_commit() {
    asm volatile("cp.async.commit_group;" ::: "memory");
}
__device__ __forceinline__ void cp_wait1() {
    asm volatile("cp.async.wait_group 1;" ::: "memory");
}

__device__ __forceinline__ void ldsm_x4(u32& r0, u32& r1, u32& r2, u32& r3, u32 a) {
    asm volatile("ldmatrix.sync.aligned.m8n8.x4.shared.b16 {%0,%1,%2,%3}, [%4];"
                 : "=r"(r0), "=r"(r1), "=r"(r2), "=r"(r3) : "r"(a));
}
__device__ __forceinline__ void hmma_f16(float* c, const u32* a, u32 b0, u32 b1) {
    asm volatile(
        "mma.sync.aligned.m16n8k16.row.col.f32.f16.f16.f32 "
        "{%0,%1,%2,%3}, {%4,%5,%6,%7}, {%8,%9}, {%0,%1,%2,%3};"
        : "+f"(c[0]), "+f"(c[1]), "+f"(c[2]), "+f"(c[3])
        : "r"(a[0]), "r"(a[1]), "r"(a[2]), "r"(a[3]), "r"(b0), "r"(b1));
}

// ---------------- conversion: fp32 -> fp16 (1:1) ----------------
__global__ void __launch_bounds__(256)
convert_kernel(const float* __restrict__ a, const float* __restrict__ b)
{
    constexpr size_t ACH = (size_t)RANKS * Mdim * KL / 8;   // 4,194,304
    constexpr size_t BCH = (size_t)RANKS * Ndim * KL / 8;   // 2,097,152
    size_t id = (size_t)blockIdx.x * 256 + threadIdx.x;
    if (id >= ACH + BCH) return;

    bool isA = id < ACH;
    size_t cid = isA ? id : id - ACH;

    size_t src_row = cid >> 6;            // 64 chunks of 8 floats per (src,row)
    int k0 = (int)(cid & 63) * 8;
    int srk, row;
    if (isA) { srk = (int)(src_row / Mdim); row = (int)(src_row % Mdim); }
    else     { srk = (int)(src_row / Ndim); row = (int)(src_row % Ndim); }

    const float* src = (isA ? a : b) + cid * 8;
    __half* dst = (isA ? g_A2 : g_B2)
        + (size_t)row * K4 + (size_t)(srk * KL + k0);

    float4 f0 = ((const float4*)src)[0];
    float4 f1 = ((const float4*)src)[1];
    float xs[8] = {f0.x, f0.y, f0.z, f0.w, f1.x, f1.y, f1.z, f1.w};

    __align__(16) __half ov[8];
#pragma unroll
    for (int i = 0; i < 8; i++) ov[i] = __float2half_rn(xs[i]);
    *(uint4*)dst = *(const uint4*)ov;
}

// ---------------- HMMA GEMM: C[8192,4096] = A2 @ B2^T ----------------
__global__ void __launch_bounds__(THREADS, 2)
gemm_mma_kernel(float* __restrict__ C)
{
    extern __shared__ __align__(1024) char smem[];
    const u32 sbase = smem_u32(smem);
    const int tid = threadIdx.x;
    const int lane = tid & 31;
    const int w = tid >> 5;            // 8 warps
    const int wm = w >> 2;             // 0..1 : warp row (64 M each)
    const int wn = w & 3;              // 0..3 : warp col (32 N each)

    const int m0 = blockIdx.y * BM;
    const int n0 = blockIdx.x * BN;

    // ---- cp.async mapping: 8 chunks/thread/stage (4 A + 4 B) ----
    const int lrow = tid >> 3;                    // 0..31
    const int lcol = tid & 7;                     // 0..7
    const u32 sA0 = swz128((u32)lrow * 128 + (u32)lcol * 16);
    const u32 sB0 = A_BYTES + sA0;                // same swizzle key (row&7 equal)
    const __half* gA = g_A2 + (size_t)(m0 + lrow) * K4 + lcol * 8;
    const __half* gB = g_B2 + (size_t)(n0 + lrow) * K4 + lcol * 8;
    constexpr size_t RSTRIDE = (size_t)32 * K4;   // 32-row pointer stride

    // ---- ldmatrix address precomputation ----
    const u32 frag_xor = (u32)(lane & 7) * 16;
    const u32 khalf = (u32)((lane >> 4) & 1) * 16;
    const int frag_row = (((lane >> 3) & 1) << 3) + (lane & 7);
    u32 aPre[4];
#pragma unroll
    for (int mb = 0; mb < 4; mb++)
        aPre[mb] = (u32)(wm * 64 + mb * 16 + frag_row) * 128;
    u32 bPre[2];
#pragma unroll
    for (int nb = 0; nb < 2; nb++)
        bPre[nb] = (u32)(wn * 32 + nb * 16 + frag_row) * 128;

    float acc[4][4][4];
#pragma unroll
    for (int i = 0; i < 4; i++)
#pragma unroll
        for (int j = 0; j < 4; j++)
#pragma unroll
            for (int q = 0; q < 4; q++) acc[i][j][q] = 0.f;

    // ---- prologue: stage tiles 0..1 ----
#pragma unroll
    for (int p = 0; p < 2; p++) {
        const u32 sb = sbase + p * STAGE_BYTES;
#pragma unroll
        for (int i = 0; i < 4; i++)
            cp_async16(sb + sA0 + i * 4096, gA + (size_t)i * RSTRIDE + (size_t)p * BKB);
#pragma unroll
        for (int j = 0; j < 4; j++)
            cp_async16(sb + sB0 + j * 4096, gB + (size_t)j * RSTRIDE + (size_t)p * BKB);
        cp_commit();
    }

    // fragment double buffers
    u32 af[2][4][4];
    u32 bf[2][2][4];

    // ---- main loop: one barrier per tile; frags double-buffered over ks ----
    // WAR safe: prefetch writes stage (t+2)%3 == (t-1)%3, whose readers
    // (compute t-1) all precede this iteration's __syncthreads.
    int stage = 0;
    for (int t = 0; t < NT; t++) {
        cp_wait1();                // tile t's group complete (own thread)
        __syncthreads();           // all threads' chunks of tile t visible

        if (t + 2 < NT) {
            int ps = stage + 2; if (ps >= 3) ps -= 3;
            const u32 sb = sbase + ps * STAGE_BYTES;
#pragma unroll
            for (int i = 0; i < 4; i++)
                cp_async16(sb + sA0 + i * 4096,
                           gA + (size_t)i * RSTRIDE + (size_t)(t + 2) * BKB);
#pragma unroll
            for (int j = 0; j < 4; j++)
                cp_async16(sb + sB0 + j * 4096,
                           gB + (size_t)j * RSTRIDE + (size_t)(t + 2) * BKB);
        }
        cp_commit();               // one group per iter (empty near tail)

        const u32 sA = sbase + stage * STAGE_BYTES;
        const u32 sB = sA + A_BYTES;

        // load ks=0 fragments
        {
            const u32 kk = khalf ^ frag_xor;
#pragma unroll
            for (int mb = 0; mb < 4; mb++)
                ldsm_x4(af[0][mb][0], af[0][mb][1], af[0][mb][2], af[0][mb][3],
                        sA + aPre[mb] + kk);
#pragma unroll
            for (int nb = 0; nb < 2; nb++)
                ldsm_x4(bf[0][nb][0], bf[0][nb][1], bf[0][nb][2], bf[0][nb][3],
                        sB + bPre[nb] + kk);
        }

#pragma unroll
        for (int ks = 0; ks < 4; ks++) {
            const int cur = ks & 1;
            if (ks < 3) {           // prefetch next ks fragments before HMMAs
                const int nxt = cur ^ 1;
                const u32 kk = ((u32)(ks + 1) * 32 + khalf) ^ frag_xor;
#pragma unroll
                for (int mb = 0; mb < 4; mb++)
                    ldsm_x4(af[nxt][mb][0], af[nxt][mb][1], af[nxt][mb][2], af[nxt][mb][3],
                            sA + aPre[mb] + kk);
#pragma unroll
                for (int nb = 0; nb < 2; nb++)
                    ldsm_x4(bf[nxt][nb][0], bf[nxt][nb][1], bf[nxt][nb][2], bf[nxt][nb][3],
                            sB + bPre[nb] + kk);
            }
#pragma unroll
            for (int mb = 0; mb < 4; mb++)
#pragma unroll
                for (int nb = 0; nb < 2; nb++) {
                    hmma_f16(acc[mb][2 * nb + 0], af[cur][mb], bf[cur][nb][0], bf[cur][nb][2]);
                    hmma_f16(acc[mb][2 * nb + 1], af[cur][mb], bf[cur][nb][1], bf[cur][nb][3]);
                }
        }

        if (++stage == 3) stage = 0;
    }

    // ---- epilogue ----
    const int er = lane >> 2;
    const int ec = (lane & 3) * 2;
#pragma unroll
    for (int mb = 0; mb < 4; mb++) {
#pragma unroll
        for (int nb = 0; nb < 4; nb++) {
            float* base = C + (size_t)(m0 + wm * 64 + mb * 16 + er) * Ndim
                            + (n0 + wn * 32 + nb * 8 + ec);
            *(float2*)base = make_float2(acc[mb][nb][0], acc[mb][nb][1]);
            *(float2*)(base + (size_t)8 * Ndim) = make_float2(acc[mb][nb][2], acc[mb][nb][3]);
        }
    }
}

// ---------------- launch ----------------
extern "C" void kernel_launch(void* const* d_in, const int* in_sizes, int n_in,
                              void* d_out, int out_size)
{
    const float* a = (const float*)d_in[0];   // [8, 8192, 512] fp32
    const float* b = (const float*)d_in[1];   // [8, 4096, 512] fp32
    float* c = (float*)d_out;                 // [8192, 4096] fp32

    constexpr size_t TOTAL_CHUNKS =
        ((size_t)RANKS * Mdim * KL + (size_t)RANKS * Ndim * KL) / 8;  // 6,291,456
    convert_kernel<<<(unsigned)(TOTAL_CHUNKS / 256), 256>>>(a, b);

    cudaFuncSetAttribute(gemm_mma_kernel,
                         cudaFuncAttributeMaxDynamicSharedMemorySize, SMEM_TOTAL);
    dim3 grid(Ndim / BN, Mdim / BM);          // (32, 64) = 2048 CTAs, 2 per SM
    gemm_mma_kernel<<<grid, THREADS, SMEM_TOTAL>>>(c);
}